// round 2
// baseline (speedup 1.0000x reference)
#include <cuda_runtime.h>
#include <math.h>

// Problem constants (fixed by reference setup_inputs)
#define BSZ   4096
#define D0    2048
#define D1    128
#define NTOT  8192            // 2*BSZ
#define TILE  64
#define BK    32
#define NTILES (NTOT / TILE)  // 128
// Flag threshold on l2 of feature 1. exp(-130/1.68) ~ 2.6e-34; dropped mass
// bounded by N^2 * 5 * 2.6e-34 ~ 9e-26 absolute vs answer ~2.4e-3. Provably safe.
#define L2_THRESH 130.0f

// ---- scratch (allocation-free rule: __device__ globals) ----
__device__ float  g_sq0[NTOT];
__device__ float  g_sq1[NTOT];
__device__ float  g_colsum[D0];
__device__ double g_sum_sq0;
__device__ double g_acc;
__device__ float  g_inv_bw[5];

// ---------------------------------------------------------------------------
// K0: zero the accumulators (must re-run every graph replay)
// ---------------------------------------------------------------------------
__global__ void k_init() {
    int i = blockIdx.x * blockDim.x + threadIdx.x;
    if (i < D0) g_colsum[i] = 0.0f;
    if (i == 0) { g_sum_sq0 = 0.0; g_acc = 0.0; }
}

// ---------------------------------------------------------------------------
// K1: per-row sum of squares for feature0 (2048) and feature1 (128)
// ---------------------------------------------------------------------------
__global__ __launch_bounds__(256) void k_rows(
    const float* __restrict__ src0, const float* __restrict__ tar0,
    const float* __restrict__ src1, const float* __restrict__ tar1)
{
    int n = blockIdx.x;
    int t = threadIdx.x;
    const float* r0 = (n < BSZ) ? (src0 + (size_t)n * D0) : (tar0 + (size_t)(n - BSZ) * D0);
    const float* r1 = (n < BSZ) ? (src1 + (size_t)n * D1) : (tar1 + (size_t)(n - BSZ) * D1);

    float s = 0.0f;
    const float4* p4 = (const float4*)r0;    // 512 float4
#pragma unroll
    for (int j = 0; j < 2; j++) {
        float4 v = p4[t + j * 256];
        s += v.x * v.x + v.y * v.y + v.z * v.z + v.w * v.w;
    }
    __shared__ float red[256];
    red[t] = s;
    __syncthreads();
    for (int off = 128; off > 0; off >>= 1) {
        if (t < off) red[t] += red[t + off];
        __syncthreads();
    }
    if (t == 0) {
        g_sq0[n] = red[0];
        atomicAdd(&g_sum_sq0, (double)red[0]);
    }
    __syncthreads();

    float s1 = 0.0f;
    if (t < D1) { float v = r1[t]; s1 = v * v; }
    red[t] = s1;
    __syncthreads();
    for (int off = 128; off > 0; off >>= 1) {
        if (t < off) red[t] += red[t + off];
        __syncthreads();
    }
    if (t == 0) g_sq1[n] = red[0];
}

// ---------------------------------------------------------------------------
// K2: column sums of feature0 (for analytic sum of l2 -> bandwidth)
// grid (8, 8): x = d-block of 256 columns, y = 1024-row chunk
// ---------------------------------------------------------------------------
__global__ __launch_bounds__(256) void k_col(
    const float* __restrict__ src0, const float* __restrict__ tar0)
{
    int d = blockIdx.x * 256 + threadIdx.x;
    int chunk = blockIdx.y;  // 0..7; chunks 0..3 -> src, 4..7 -> tar
    const float* base = (chunk < 4) ? (src0 + (size_t)chunk * 1024 * D0)
                                    : (tar0 + (size_t)(chunk - 4) * 1024 * D0);
    float s = 0.0f;
#pragma unroll 8
    for (int n = 0; n < 1024; n++) s += base[(size_t)n * D0 + d];
    atomicAdd(&g_colsum[d], s);
}

// ---------------------------------------------------------------------------
// K3: finalize bandwidth: sum_l2 = 2N*sum_sq0 - 2*||colsum||^2
// ---------------------------------------------------------------------------
__global__ __launch_bounds__(256) void k_bw() {
    int t = threadIdx.x;
    double s = 0.0;
    for (int d = t; d < D0; d += 256) {
        double c = (double)g_colsum[d];
        s += c * c;
    }
    __shared__ double red[256];
    red[t] = s;
    __syncthreads();
    for (int off = 128; off > 0; off >>= 1) {
        if (t < off) red[t] += red[t + off];
        __syncthreads();
    }
    if (t == 0) {
        double sum_l2 = 2.0 * (double)NTOT * g_sum_sq0 - 2.0 * red[0];
        double bw = sum_l2 / ((double)NTOT * (double)NTOT - (double)NTOT) / 4.0;
#pragma unroll
        for (int i = 0; i < 5; i++)
            g_inv_bw[i] = (float)(1.0 / (bw * (double)(1 << i)));
    }
}

// ---------------------------------------------------------------------------
// K4: fused classifier GEMM (feature1, fp32) + sparse exact epilogue.
// 64x64 tiles, 256 threads, 4x4 register blocking, K chunked by 32.
// Upper-triangle tiles only (weight 2 off-diag, 1 on diag).
// ---------------------------------------------------------------------------
__global__ __launch_bounds__(256) void k_tile(
    const float* __restrict__ src0, const float* __restrict__ tar0,
    const float* __restrict__ src1, const float* __restrict__ tar1)
{
    int bx = blockIdx.x;  // column tile
    int by = blockIdx.y;  // row tile
    if (bx < by) return;  // symmetry: only upper triangle

    __shared__ float As[TILE][BK + 1];
    __shared__ float Bs[TILE][BK + 1];

    int tid = threadIdx.x;
    int tx = tid & 15;
    int ty = tid >> 4;

    float acc[4][4] = {};
    int arow0 = by * TILE;
    int brow0 = bx * TILE;

    for (int k0 = 0; k0 < D1; k0 += BK) {
        __syncthreads();
        for (int idx = tid; idx < TILE * BK; idx += 256) {
            int r = idx >> 5;         // row within tile
            int k = idx & 31;         // k within chunk
            int an = arow0 + r;
            const float* pa = (an < BSZ) ? (src1 + (size_t)an * D1)
                                         : (tar1 + (size_t)(an - BSZ) * D1);
            As[r][k] = pa[k0 + k];
            int bn = brow0 + r;
            const float* pb = (bn < BSZ) ? (src1 + (size_t)bn * D1)
                                         : (tar1 + (size_t)(bn - BSZ) * D1);
            Bs[r][k] = pb[k0 + k];
        }
        __syncthreads();

#pragma unroll
        for (int k = 0; k < BK; k++) {
            float a[4], b[4];
#pragma unroll
            for (int i = 0; i < 4; i++) a[i] = As[ty * 4 + i][k];
#pragma unroll
            for (int j = 0; j < 4; j++) b[j] = Bs[tx * 4 + j][k];
#pragma unroll
            for (int i = 0; i < 4; i++)
#pragma unroll
                for (int j = 0; j < 4; j++)
                    acc[i][j] += a[i] * b[j];
        }
    }

    // Epilogue: threshold test; flagged pairs computed exactly.
    float sqa[4], sqb[4];
#pragma unroll
    for (int i = 0; i < 4; i++) sqa[i] = g_sq1[arow0 + ty * 4 + i];
#pragma unroll
    for (int j = 0; j < 4; j++) sqb[j] = g_sq1[brow0 + tx * 4 + j];

    float local = 0.0f;
#pragma unroll
    for (int i = 0; i < 4; i++) {
#pragma unroll
        for (int j = 0; j < 4; j++) {
            float l2 = sqa[i] + sqb[j] - 2.0f * acc[i][j];
            if (l2 < L2_THRESH) {
                int a = arow0 + ty * 4 + i;
                int b = brow0 + tx * 4 + j;
                float k1v = expf(-l2 * (1.0f / 1.68f));
                float l20;
                if (a == b) {
                    l20 = 0.0f;  // sq[a]+sq[a]-2*dot(a,a) == 0 by construction
                } else {
                    const float* ra = (a < BSZ) ? (src0 + (size_t)a * D0)
                                                : (tar0 + (size_t)(a - BSZ) * D0);
                    const float* rb = (b < BSZ) ? (src0 + (size_t)b * D0)
                                                : (tar0 + (size_t)(b - BSZ) * D0);
                    float dp = 0.0f;
                    for (int d = 0; d < D0; d += 4) {
                        float4 x = *(const float4*)(ra + d);
                        float4 y = *(const float4*)(rb + d);
                        dp += x.x * y.x + x.y * y.y + x.z * y.z + x.w * y.w;
                    }
                    l20 = g_sq0[a] + g_sq0[b] - 2.0f * dp;
                }
                float k0v = 0.0f;
#pragma unroll
                for (int q = 0; q < 5; q++) k0v += expf(-l20 * g_inv_bw[q]);
                local += k0v * k1v;
            }
        }
    }

    // block reduce + signed/weighted accumulate
    __shared__ float redf[256];
    redf[tid] = local;
    __syncthreads();
    for (int off = 128; off > 0; off >>= 1) {
        if (tid < off) redf[tid] += redf[tid + off];
        __syncthreads();
    }
    if (tid == 0 && redf[0] != 0.0f) {
        float w = (bx == by) ? 1.0f : 2.0f;
        float sgn = ((by < NTILES / 2) == (bx < NTILES / 2)) ? 1.0f : -1.0f;
        atomicAdd(&g_acc, (double)(redf[0] * w * sgn));
    }
}

// ---------------------------------------------------------------------------
// K5: write scalar output
// ---------------------------------------------------------------------------
__global__ void k_out(float* __restrict__ out) {
    out[0] = (float)(g_acc / ((double)BSZ * (double)BSZ));
}

extern "C" void kernel_launch(void* const* d_in, const int* in_sizes, int n_in,
                              void* d_out, int out_size)
{
    const float* src0 = (const float*)d_in[0];
    const float* src1 = (const float*)d_in[1];
    const float* tar0 = (const float*)d_in[2];
    const float* tar1 = (const float*)d_in[3];
    float* out = (float*)d_out;

    k_init<<<8, 256>>>();
    k_rows<<<NTOT, 256>>>(src0, tar0, src1, tar1);
    k_col<<<dim3(8, 8), 256>>>(src0, tar0);
    k_bw<<<1, 256>>>();
    k_tile<<<dim3(NTILES, NTILES), 256>>>(src0, tar0, src1, tar1);
    k_out<<<1, 1>>>(out);
}

// round 5
// speedup vs baseline: 1.9254x; 1.9254x over previous
#include <cuda_runtime.h>
#include <cuda_bf16.h>
#include <math.h>
#include <cstdint>

// Problem constants (fixed by reference setup_inputs)
#define BSZ   4096
#define D0    2048
#define D1    128
#define NTOT  8192
#define TM    128            // screening tile dim
#define NT    (NTOT / TM)    // 64 tiles per side
// bf16 screening threshold: true-l2 threshold 130 plus margin for bf16 dot error
// (bounded ~ +-6); screen at 145, exact fp32 re-test at 130. exp(-130/1.68)~2.6e-34,
// dropped mass < N^2*5*2.6e-34 ~ 9e-26 vs answer ~2.4e-3 -> provably negligible.
#define SCREEN_T 145.0f
#define EXACT_T  130.0f

#define SPAD  72             // smem row stride in bf16 (144B: 8B-aligned, ldmatrix conflict-free)

// ---- scratch (allocation-free rule: __device__ globals) ----
__device__ float  g_sq0[NTOT];
__device__ float  g_sq1[NTOT];
__device__ float  g_colsum[D0];
__device__ double g_sum_sq0;
__device__ double g_acc;
__device__ float  g_inv_bw[5];
__device__ __nv_bfloat16 g_x1[(size_t)NTOT * D1];   // bf16 copy of feature1 (2 MB)

__device__ __forceinline__ uint32_t smem_u32(const void* p) {
    uint32_t a;
    asm("{ .reg .u64 t; cvta.to.shared.u64 t, %1; cvt.u32.u64 %0, t; }"
        : "=r"(a) : "l"(p));
    return a;
}

// ---------------------------------------------------------------------------
// K0: zero accumulators (must re-run every graph replay)
// ---------------------------------------------------------------------------
__global__ void k_init() {
    int i = blockIdx.x * 256 + threadIdx.x;
    if (i < D0) g_colsum[i] = 0.0f;
    if (i < NTOT) g_sq0[i] = 0.0f;
    if (i == 0) { g_sum_sq0 = 0.0; g_acc = 0.0; }
}

// ---------------------------------------------------------------------------
// K1: convert feature1 to bf16 + per-row sq1 (one 128-thread block per row)
// ---------------------------------------------------------------------------
__global__ __launch_bounds__(128) void k_conv(
    const float* __restrict__ src1, const float* __restrict__ tar1)
{
    int n = blockIdx.x;
    int t = threadIdx.x;
    const float* r1 = (n < BSZ) ? (src1 + (size_t)n * D1)
                                : (tar1 + (size_t)(n - BSZ) * D1);
    float v = r1[t];
    g_x1[(size_t)n * D1 + t] = __float2bfloat16(v);
    float s = v * v;
#pragma unroll
    for (int off = 16; off; off >>= 1) s += __shfl_xor_sync(0xffffffffu, s, off);
    __shared__ float red[4];
    if ((t & 31) == 0) red[t >> 5] = s;
    __syncthreads();
    if (t == 0) g_sq1[n] = red[0] + red[1] + red[2] + red[3];
}

// ---------------------------------------------------------------------------
// K2: fused single pass over feature0 (64 MB): row sq0 + col sums + total sq
// grid (8, 8): x = 256-col block, y = 1024-row chunk
// ---------------------------------------------------------------------------
__global__ __launch_bounds__(256) void k_f0(
    const float* __restrict__ src0, const float* __restrict__ tar0)
{
    int w = threadIdx.x >> 5, l = threadIdx.x & 31;
    int d0 = blockIdx.x * 256;
    int nbase = blockIdx.y * 1024 + w * 128;
    float colacc[8] = {};
    double wsum = 0.0;
    for (int rr = 0; rr < 128; rr++) {
        int n = nbase + rr;
        const float* p = (n < BSZ) ? (src0 + (size_t)n * D0)
                                   : (tar0 + (size_t)(n - BSZ) * D0);
        float sq = 0.0f;
#pragma unroll
        for (int j = 0; j < 8; j++) {
            float v = p[d0 + l + j * 32];
            sq += v * v;
            colacc[j] += v;
        }
#pragma unroll
        for (int off = 16; off; off >>= 1)
            sq += __shfl_xor_sync(0xffffffffu, sq, off);
        if (l == 0) { atomicAdd(&g_sq0[n], sq); wsum += (double)sq; }
    }
    if (l == 0) atomicAdd(&g_sum_sq0, wsum);
#pragma unroll
    for (int j = 0; j < 8; j++)
        atomicAdd(&g_colsum[d0 + l + j * 32], colacc[j]);
}

// ---------------------------------------------------------------------------
// K3: finalize bandwidth: sum_l2 = 2N*sum_sq0 - 2*||colsum||^2
// ---------------------------------------------------------------------------
__global__ __launch_bounds__(256) void k_bw() {
    int t = threadIdx.x;
    double s = 0.0;
#pragma unroll
    for (int j = 0; j < 8; j++) {
        double c = (double)g_colsum[t + j * 256];
        s += c * c;
    }
#pragma unroll
    for (int off = 16; off; off >>= 1)
        s += __shfl_xor_sync(0xffffffffu, s, off);
    __shared__ double red[8];
    if ((t & 31) == 0) red[t >> 5] = s;
    __syncthreads();
    if (t == 0) {
        double tot = 0.0;
#pragma unroll
        for (int i = 0; i < 8; i++) tot += red[i];
        double sum_l2 = 2.0 * (double)NTOT * g_sum_sq0 - 2.0 * tot;
        double bw = sum_l2 / ((double)NTOT * (double)NTOT - (double)NTOT) / 4.0;
#pragma unroll
        for (int i = 0; i < 5; i++)
            g_inv_bw[i] = (float)(1.0 / (bw * (double)(1 << i)));
    }
}

// ---------------------------------------------------------------------------
// K4: bf16 HMMA screening GEMM (128x128 tiles, mma.sync m16n8k16)
// + sparse exact fp32 epilogue. Upper-triangle tiles only.
// 256 threads = 8 warps in a 4(row)x2(col) grid; warp tile 32x64.
// Both A and B are K-contiguous in SMEM -> plain (non-trans) ldmatrix for both.
// ---------------------------------------------------------------------------
__global__ __launch_bounds__(256) void k_tile(
    const float* __restrict__ src0, const float* __restrict__ tar0,
    const float* __restrict__ src1, const float* __restrict__ tar1)
{
    int bx = blockIdx.x, by = blockIdx.y;
    if (bx < by) return;                 // symmetry: upper triangle only

    __shared__ __nv_bfloat16 As[TM][SPAD];   // 18 KB (one 64-col K chunk)
    __shared__ __nv_bfloat16 Bs[TM][SPAD];   // 18 KB
    __shared__ float sqb[TM];
    __shared__ float wred[8];

    int tid = threadIdx.x;
    int wid = tid >> 5, lane = tid & 31;
    int wy = wid >> 1, wx = wid & 1;     // warp grid 4x2
    int arow0 = by * TM, brow0 = bx * TM;

    if (tid < TM) sqb[tid] = g_sq1[brow0 + tid];

    float acc[2][8][4];
#pragma unroll
    for (int mt = 0; mt < 2; mt++)
#pragma unroll
        for (int nt = 0; nt < 8; nt++)
#pragma unroll
            for (int v = 0; v < 4; v++) acc[mt][nt][v] = 0.0f;

    // ldmatrix x4 lane->row mapping (matrices 0..3 = lane groups 0-7/8-15/16-23/24-31):
    //   A (m16 x k16): m0=rows0-7,k0-7  m1=rows8-15,k0-7  m2=rows0-7,k8-15  m3=rows8-15,k8-15
    //     row = lane&15, kof = (lane>>4)*8      -> regs a0..a3 in mma order
    //   B (n16 x k16 per np): same matrix order over n-rows
    //     row = ((lane>>3)&1)*8 + (lane&7), kof = (lane>>4)*8
    //     then nt even: b0=r0,b1=r2 ; nt odd: b0=r1,b1=r3
    uint32_t aRow = (uint32_t)(wy * 32 + (lane & 15));
    uint32_t aKof = (uint32_t)((lane >> 4) * 8);
    uint32_t bRowBase = (uint32_t)(wx * 64 + ((lane >> 3) & 1) * 8 + (lane & 7));
    uint32_t bKof = (uint32_t)((lane >> 4) * 8);
    uint32_t sA = smem_u32(As), sB = smem_u32(Bs);

    for (int kc = 0; kc < 2; kc++) {     // two 64-wide K chunks
        __syncthreads();
        // fill SMEM: 128 rows x 64 bf16 per matrix, 8B (uint2) stores
        for (int idx = tid; idx < TM * 16; idx += 256) {
            int r = idx >> 4;
            int c = idx & 15;            // uint2 index within 64-col row
            const uint2* pa = (const uint2*)(g_x1 + (size_t)(arow0 + r) * D1 + kc * 64) + c;
            const uint2* pb = (const uint2*)(g_x1 + (size_t)(brow0 + r) * D1 + kc * 64) + c;
            *(uint2*)(&As[r][c * 4]) = *pa;
            *(uint2*)(&Bs[r][c * 4]) = *pb;
        }
        __syncthreads();

#pragma unroll
        for (int ks = 0; ks < 4; ks++) { // K16 steps within chunk
            uint32_t a[2][4];
#pragma unroll
            for (int mt = 0; mt < 2; mt++) {
                uint32_t addr = sA + ((aRow + mt * 16) * SPAD + ks * 16 + aKof) * 2;
                asm volatile(
                    "ldmatrix.sync.aligned.m8n8.x4.shared.b16 {%0,%1,%2,%3}, [%4];"
                    : "=r"(a[mt][0]), "=r"(a[mt][1]), "=r"(a[mt][2]), "=r"(a[mt][3])
                    : "r"(addr));
            }
            uint32_t b[4][4];
#pragma unroll
            for (int np = 0; np < 4; np++) {
                uint32_t addr = sB + ((bRowBase + np * 16) * SPAD + ks * 16 + bKof) * 2;
                asm volatile(
                    "ldmatrix.sync.aligned.m8n8.x4.shared.b16 {%0,%1,%2,%3}, [%4];"
                    : "=r"(b[np][0]), "=r"(b[np][1]), "=r"(b[np][2]), "=r"(b[np][3])
                    : "r"(addr));
            }
#pragma unroll
            for (int mt = 0; mt < 2; mt++)
#pragma unroll
                for (int nt = 0; nt < 8; nt++) {
                    uint32_t b0 = b[nt >> 1][(nt & 1)];
                    uint32_t b1 = b[nt >> 1][(nt & 1) + 2];
                    float* c = acc[mt][nt];
                    asm volatile(
                        "mma.sync.aligned.m16n8k16.row.col.f32.bf16.bf16.f32 "
                        "{%0,%1,%2,%3}, {%4,%5,%6,%7}, {%8,%9}, {%0,%1,%2,%3};"
                        : "+f"(c[0]), "+f"(c[1]), "+f"(c[2]), "+f"(c[3])
                        : "r"(a[mt][0]), "r"(a[mt][1]), "r"(a[mt][2]), "r"(a[mt][3]),
                          "r"(b0), "r"(b1));
                }
        }
    }

    // ---- Epilogue: screen, exact fp32 recompute for flagged pairs ----
    // c[v] owner: row = base + (lane>>2) + 8*(v>>1), col = base + (lane&3)*2 + (v&1)
    float sqa0 = g_sq1[arow0 + wy * 32 + (lane >> 2)];
    float sqa1 = g_sq1[arow0 + wy * 32 + (lane >> 2) + 8];
    float sqa2 = g_sq1[arow0 + wy * 32 + 16 + (lane >> 2)];
    float sqa3 = g_sq1[arow0 + wy * 32 + 16 + (lane >> 2) + 8];

    float local = 0.0f;
#pragma unroll
    for (int mt = 0; mt < 2; mt++) {
#pragma unroll
        for (int nt = 0; nt < 8; nt++) {
#pragma unroll
            for (int v = 0; v < 4; v++) {
                int arow = wy * 32 + mt * 16 + (lane >> 2) + 8 * (v >> 1);
                int col  = wx * 64 + nt * 8 + (lane & 3) * 2 + (v & 1);
                float sqa = mt ? ((v >> 1) ? sqa3 : sqa2) : ((v >> 1) ? sqa1 : sqa0);
                float l2s = sqa + sqb[col] - 2.0f * acc[mt][nt][v];
                if (l2s < SCREEN_T) {
                    int aa = arow0 + arow;
                    int bb = brow0 + col;
                    float contrib = 0.0f;
                    if (aa == bb) {
                        contrib = 5.0f;   // k1=1, k0=5 at l2=0
                    } else {
                        const float* ra1 = (aa < BSZ) ? (src1 + (size_t)aa * D1)
                                                      : (tar1 + (size_t)(aa - BSZ) * D1);
                        const float* rb1 = (bb < BSZ) ? (src1 + (size_t)bb * D1)
                                                      : (tar1 + (size_t)(bb - BSZ) * D1);
                        float dp1 = 0.0f;
                        for (int dd = 0; dd < D1; dd += 4) {
                            float4 x = *(const float4*)(ra1 + dd);
                            float4 y = *(const float4*)(rb1 + dd);
                            dp1 += x.x * y.x + x.y * y.y + x.z * y.z + x.w * y.w;
                        }
                        float l21 = sqa + g_sq1[bb] - 2.0f * dp1;
                        if (l21 < EXACT_T) {
                            float k1v = expf(-l21 * (1.0f / 1.68f));
                            const float* ra0 = (aa < BSZ) ? (src0 + (size_t)aa * D0)
                                                          : (tar0 + (size_t)(aa - BSZ) * D0);
                            const float* rb0 = (bb < BSZ) ? (src0 + (size_t)bb * D0)
                                                          : (tar0 + (size_t)(bb - BSZ) * D0);
                            float dp0 = 0.0f;
                            for (int dd = 0; dd < D0; dd += 4) {
                                float4 x = *(const float4*)(ra0 + dd);
                                float4 y = *(const float4*)(rb0 + dd);
                                dp0 += x.x * y.x + x.y * y.y + x.z * y.z + x.w * y.w;
                            }
                            float l20 = g_sq0[aa] + g_sq0[bb] - 2.0f * dp0;
                            float k0v = 0.0f;
#pragma unroll
                            for (int q = 0; q < 5; q++)
                                k0v += expf(-l20 * g_inv_bw[q]);
                            contrib = k0v * k1v;
                        }
                    }
                    local += contrib;
                }
            }
        }
    }

    // reduce + signed/weighted accumulate
#pragma unroll
    for (int off = 16; off; off >>= 1)
        local += __shfl_xor_sync(0xffffffffu, local, off);
    if (lane == 0) wred[wid] = local;
    __syncthreads();
    if (tid == 0) {
        float r = 0.0f;
#pragma unroll
        for (int i = 0; i < 8; i++) r += wred[i];
        if (r != 0.0f) {
            float w   = (bx == by) ? 1.0f : 2.0f;
            float sgn = ((by < NT / 2) == (bx < NT / 2)) ? 1.0f : -1.0f;
            atomicAdd(&g_acc, (double)(r * w * sgn));
        }
    }
}

// ---------------------------------------------------------------------------
// K5: write scalar output
// ---------------------------------------------------------------------------
__global__ void k_out(float* __restrict__ out) {
    out[0] = (float)(g_acc / ((double)BSZ * (double)BSZ));
}

extern "C" void kernel_launch(void* const* d_in, const int* in_sizes, int n_in,
                              void* d_out, int out_size)
{
    const float* src0 = (const float*)d_in[0];
    const float* src1 = (const float*)d_in[1];
    const float* tar0 = (const float*)d_in[2];
    const float* tar1 = (const float*)d_in[3];
    float* out = (float*)d_out;

    k_init<<<32, 256>>>();
    k_conv<<<NTOT, 128>>>(src1, tar1);
    k_f0<<<dim3(8, 8), 256>>>(src0, tar0);
    k_bw<<<1, 256>>>();
    k_tile<<<dim3(NT, NT), 256>>>(src0, tar0, src1, tar1);
    k_out<<<1, 1>>>(out);
}